// round 15
// baseline (speedup 1.0000x reference)
#include <cuda_runtime.h>
#include <cuda_fp16.h>
#include <cstdint>

#define D 64
#define NMAX 50000
#define TILE_M 128
#define LDX 72            // halves per SMEM row: 144B = 9*16B -> ldmatrix conflict-free
#define CAP 128           // per-node bucket capacity (max degree ~60, 14-sigma margin)

// ---------------- device scratch (no allocation allowed) ----------------
__device__ __half g_mh[NMAX * D];        // per-node message table (fp16)
__device__ float  g_z[NMAX * D];         // segment-sum result (fp32)
__device__ int    g_cnt[NMAX];           // per-node edge counts
__device__ int    g_bucket[NMAX * CAP];  // per-node src lists (fixed stride)

// SMEM: Xh[128][LDX] fp16 (reused for H1), W1h/W2h[64][LDX] fp16, b1s/b2s[64] f32
#define SMEM_MMA_BYTES (128 * LDX * 2 + 2 * 64 * LDX * 2 + 2 * 64 * 4 + 64)

// ---------------- PTX helpers ----------------
__device__ __forceinline__ uint32_t smem_u32(const void* p) {
    uint32_t a;
    asm("{ .reg .u64 t; cvta.to.shared.u64 t, %1; cvt.u32.u64 %0, t; }"
        : "=r"(a) : "l"(p));
    return a;
}
__device__ __forceinline__ void ldsm_x4(uint32_t& r0, uint32_t& r1,
                                        uint32_t& r2, uint32_t& r3, uint32_t addr) {
    asm volatile("ldmatrix.sync.aligned.m8n8.x4.shared.b16 {%0,%1,%2,%3}, [%4];"
                 : "=r"(r0), "=r"(r1), "=r"(r2), "=r"(r3) : "r"(addr));
}
__device__ __forceinline__ void ldsm_x2t(uint32_t& r0, uint32_t& r1, uint32_t addr) {
    asm volatile("ldmatrix.sync.aligned.m8n8.x2.trans.shared.b16 {%0,%1}, [%2];"
                 : "=r"(r0), "=r"(r1) : "r"(addr));
}
__device__ __forceinline__ void mma16816(float& d0, float& d1, float& d2, float& d3,
                                         uint32_t a0, uint32_t a1, uint32_t a2, uint32_t a3,
                                         uint32_t b0, uint32_t b1) {
    asm volatile(
        "mma.sync.aligned.m16n8k16.row.col.f32.f16.f16.f32 "
        "{%0,%1,%2,%3}, {%4,%5,%6,%7}, {%8,%9}, {%0,%1,%2,%3};"
        : "+f"(d0), "+f"(d1), "+f"(d2), "+f"(d3)
        : "r"(a0), "r"(a1), "r"(a2), "r"(a3), "r"(b0), "r"(b1));
}

// ---------------------------------------------------------------------------
// Tensor-core 2-layer MLP over node range [m_begin, n_limit).
// ILP layout: f outer / nt inner (8 parallel accumulator chains).
// ---------------------------------------------------------------------------
template <typename OutT>
__global__ __launch_bounds__(256) void mlp2_mma_kernel(
    const float* __restrict__ in,
    const float* __restrict__ W1, const float* __restrict__ b1,
    const float* __restrict__ W2, const float* __restrict__ b2,
    OutT* __restrict__ out, int m_begin, int n_limit)
{
    extern __shared__ __align__(16) char sm_raw[];
    __half* Xh  = (__half*)sm_raw;            // 128 x LDX (reused as H1)
    __half* W1h = Xh + 128 * LDX;             // 64 x LDX
    __half* W2h = W1h + 64 * LDX;             // 64 x LDX
    float*  b1s = (float*)(W2h + 64 * LDX);
    float*  b2s = b1s + 64;

    const int tid  = threadIdx.x;
    const int lane = tid & 31;
    const int wid  = tid >> 5;
    const int m0   = m_begin + blockIdx.x * TILE_M;

    // ---- stage weights fp32 -> fp16 ----
    for (int p = tid; p < 4096; p += 256) {
        const int r = p >> 6, c = p & 63;
        W1h[r * LDX + c] = __float2half_rn(W1[p]);
        W2h[r * LDX + c] = __float2half_rn(W2[p]);
    }
    if (tid < 64) {
        b1s[tid] = b1[tid];
        b2s[tid] = b2[tid];
    }

    // ---- stage X fp32 -> fp16 (zero-padded past n_limit) ----
    for (int p = tid; p < TILE_M * 16; p += 256) {
        const int r = p >> 4, q = p & 15;
        float4 v = make_float4(0.f, 0.f, 0.f, 0.f);
        if (m0 + r < n_limit) v = ((const float4*)in)[(size_t)(m0 + r) * 16 + q];
        __half2* dp = (__half2*)&Xh[r * LDX + q * 4];
        dp[0] = __floats2half2_rn(v.x, v.y);
        dp[1] = __floats2half2_rn(v.z, v.w);
    }
    __syncthreads();

    const int mrow = wid * 16;
    const uint32_t xrow =
        smem_u32(Xh) + (uint32_t)(((mrow + (lane & 15)) * LDX + (lane >> 4) * 8) << 1);
    const uint32_t w1b = smem_u32(W1h);
    const uint32_t w2b = smem_u32(W2h);
    const int gid = lane >> 2;
    const int tig = lane & 3;

    uint32_t a[4][4];
    float acc[8][4];   // [nt][frag]

    // ================= Layer 1 =================
#pragma unroll
    for (int f = 0; f < 4; f++)
        ldsm_x4(a[f][0], a[f][1], a[f][2], a[f][3], xrow + (uint32_t)((f * 16) << 1));

#pragma unroll
    for (int nt = 0; nt < 8; nt++)
#pragma unroll
        for (int q = 0; q < 4; q++) acc[nt][q] = 0.f;

#pragma unroll
    for (int f = 0; f < 4; f++) {
        uint32_t B[8][2];
        const uint32_t wrow = w1b + (uint32_t)(((f * 16 + (lane & 15)) * LDX) << 1);
#pragma unroll
        for (int nt = 0; nt < 8; nt++)
            ldsm_x2t(B[nt][0], B[nt][1], wrow + (uint32_t)((nt * 8) << 1));
#pragma unroll
        for (int nt = 0; nt < 8; nt++)
            mma16816(acc[nt][0], acc[nt][1], acc[nt][2], acc[nt][3],
                     a[f][0], a[f][1], a[f][2], a[f][3], B[nt][0], B[nt][1]);
    }

#pragma unroll
    for (int nt = 0; nt < 8; nt++) {
        const int c = nt * 8 + tig * 2;
        const float2 bb = *(const float2*)&b1s[c];
        const __half2 h01 = __floats2half2_rn(fmaxf(acc[nt][0] + bb.x, 0.f),
                                              fmaxf(acc[nt][1] + bb.y, 0.f));
        const __half2 h23 = __floats2half2_rn(fmaxf(acc[nt][2] + bb.x, 0.f),
                                              fmaxf(acc[nt][3] + bb.y, 0.f));
        *(__half2*)&Xh[(mrow + gid) * LDX + c]     = h01;
        *(__half2*)&Xh[(mrow + gid + 8) * LDX + c] = h23;
    }
    __syncwarp();

    // ================= Layer 2 =================
#pragma unroll
    for (int f = 0; f < 4; f++)
        ldsm_x4(a[f][0], a[f][1], a[f][2], a[f][3], xrow + (uint32_t)((f * 16) << 1));

#pragma unroll
    for (int nt = 0; nt < 8; nt++)
#pragma unroll
        for (int q = 0; q < 4; q++) acc[nt][q] = 0.f;

#pragma unroll
    for (int f = 0; f < 4; f++) {
        uint32_t B[8][2];
        const uint32_t wrow = w2b + (uint32_t)(((f * 16 + (lane & 15)) * LDX) << 1);
#pragma unroll
        for (int nt = 0; nt < 8; nt++)
            ldsm_x2t(B[nt][0], B[nt][1], wrow + (uint32_t)((nt * 8) << 1));
#pragma unroll
        for (int nt = 0; nt < 8; nt++)
            mma16816(acc[nt][0], acc[nt][1], acc[nt][2], acc[nt][3],
                     a[f][0], a[f][1], a[f][2], a[f][3], B[nt][0], B[nt][1]);
    }

#pragma unroll
    for (int nt = 0; nt < 8; nt++) {
        const int c = nt * 8 + tig * 2;
        const float2 bb = *(const float2*)&b2s[c];
        const float h0 = fmaxf(acc[nt][0] + bb.x, 0.f);
        const float h1 = fmaxf(acc[nt][1] + bb.y, 0.f);
        const float h2 = fmaxf(acc[nt][2] + bb.x, 0.f);
        const float h3 = fmaxf(acc[nt][3] + bb.y, 0.f);
        const int r0 = m0 + mrow + gid;
        const int r1 = r0 + 8;
        if constexpr (sizeof(OutT) == 4) {
            if (r0 < n_limit) *(float2*)&out[(size_t)r0 * 64 + c] = make_float2(h0, h1);
            if (r1 < n_limit) *(float2*)&out[(size_t)r1 * 64 + c] = make_float2(h2, h3);
        } else {
            if (r0 < n_limit) *(__half2*)&out[(size_t)r0 * 64 + c] = __floats2half2_rn(h0, h1);
            if (r1 < n_limit) *(__half2*)&out[(size_t)r1 * 64 + c] = __floats2half2_rn(h2, h3);
        }
    }
}

// ---------------------------------------------------------------------------
// Single-pass bucketing: pos = cnt[dst]++; bucket[dst*CAP+pos] = src.
// ---------------------------------------------------------------------------
__global__ __launch_bounds__(256) void bucket_kernel(
    const int* __restrict__ src, const int* __restrict__ dst, int e)
{
    int i = blockIdx.x * blockDim.x + threadIdx.x;
    if (i < e) {
        const int d = dst[i];
        const int pos = atomicAdd(&g_cnt[d], 1);
        if (pos < CAP)  // overflow impossible for Binomial(E,1/N) degrees (14 sigma)
            g_bucket[d * CAP + pos] = src[i];
    }
}

// ---------------------------------------------------------------------------
// Bucket aggregation over node range [node_begin, node_end).
// ---------------------------------------------------------------------------
__global__ __launch_bounds__(256) void aggregate_kernel(
    const __half2* __restrict__ m2, float2* __restrict__ z2,
    int node_begin, int node_end)
{
    const int node = node_begin + ((blockIdx.x * 256 + threadIdx.x) >> 5);
    const int lane = threadIdx.x & 31;
    if (node >= node_end) return;

    const int cnt = min(g_cnt[node], CAP);
    const int s0 = node * CAP;

    float ax = 0.f, ay = 0.f;
    for (int base = 0; base < cnt; base += 32) {
        const int c = min(32, cnt - base);
        int si = (lane < c) ? g_bucket[s0 + base + lane] : 0;
#pragma unroll 4
        for (int j = 0; j < c; j++) {
            const int s = __shfl_sync(0xffffffffu, si, j);
            const __half2 h = __ldg(&m2[(size_t)s * 32 + lane]);
            const float2 v = __half22float2(h);
            ax += v.x;
            ay += v.y;
        }
    }
    float2 o;
    o.x = ax;
    o.y = ay;
    z2[(size_t)node * 32 + lane] = o;
}

// ---------------------------------------------------------------------------
extern "C" void kernel_launch(void* const* d_in, const int* in_sizes, int n_in,
                              void* d_out, int out_size) {
    const float* y   = (const float*)d_in[0];
    const int*   src = (const int*)d_in[1];
    const int*   dst = (const int*)d_in[2];
    const float* W1  = (const float*)d_in[3];
    const float* b1  = (const float*)d_in[4];
    const float* W2  = (const float*)d_in[5];
    const float* b2  = (const float*)d_in[6];
    const float* U1  = (const float*)d_in[7];
    const float* c1  = (const float*)d_in[8];
    const float* U2  = (const float*)d_in[9];
    const float* c2  = (const float*)d_in[10];
    float* out = (float*)d_out;

    const int n = in_sizes[0] / D;
    const int e = in_sizes[1];
    const int nA = ((n / 2) + TILE_M - 1) / TILE_M * TILE_M;   // partition boundary

    __half* mh_ptr = nullptr;
    float*  z_ptr  = nullptr;
    int*    cnt_ptr = nullptr;
    cudaGetSymbolAddress((void**)&mh_ptr, g_mh);
    cudaGetSymbolAddress((void**)&z_ptr, g_z);
    cudaGetSymbolAddress((void**)&cnt_ptr, g_cnt);

    cudaFuncSetAttribute(mlp2_mma_kernel<__half>,
                         cudaFuncAttributeMaxDynamicSharedMemorySize, SMEM_MMA_BYTES);
    cudaFuncSetAttribute(mlp2_mma_kernel<float>,
                         cudaFuncAttributeMaxDynamicSharedMemorySize, SMEM_MMA_BYTES);

    static cudaStream_t s_mlp = ([] {
        cudaStream_t s;
        cudaStreamCreateWithFlags(&s, cudaStreamNonBlocking);
        return s;
    })();
    static cudaStream_t s_b = ([] {
        cudaStream_t s;
        cudaStreamCreateWithFlags(&s, cudaStreamNonBlocking);
        return s;
    })();
    static cudaEvent_t ev_fork = ([] {
        cudaEvent_t ev;
        cudaEventCreateWithFlags(&ev, cudaEventDisableTiming);
        return ev;
    })();
    static cudaEvent_t ev_mlp1 = ([] {
        cudaEvent_t ev;
        cudaEventCreateWithFlags(&ev, cudaEventDisableTiming);
        return ev;
    })();
    static cudaEvent_t ev_aggA = ([] {
        cudaEvent_t ev;
        cudaEventCreateWithFlags(&ev, cudaEventDisableTiming);
        return ev;
    })();
    static cudaEvent_t ev_B = ([] {
        cudaEvent_t ev;
        cudaEventCreateWithFlags(&ev, cudaEventDisableTiming);
        return ev;
    })();

    const int mlp1_blocks = (n + TILE_M - 1) / TILE_M;
    const int mlpA_blocks = nA / TILE_M;
    const int mlpB_blocks = (n - nA + TILE_M - 1) / TILE_M;
    const int edge_blocks = (e + 255) / 256;

    // ---- fork: mlp1 on side stream ----
    cudaEventRecord(ev_fork, (cudaStream_t)0);
    cudaStreamWaitEvent(s_mlp, ev_fork, 0);
    mlp2_mma_kernel<__half><<<mlp1_blocks, 256, SMEM_MMA_BYTES, s_mlp>>>(
        y, W1, b1, W2, b2, mh_ptr, 0, n);
    cudaEventRecord(ev_mlp1, s_mlp);

    // ---- main stream: zero counts, single-pass bucketing ----
    cudaMemsetAsync(cnt_ptr, 0, (size_t)n * sizeof(int));
    bucket_kernel<<<edge_blocks, 256>>>(src, dst, e);

    // ---- partition A: aggregate then MLP (main stream) ----
    cudaStreamWaitEvent((cudaStream_t)0, ev_mlp1, 0);
    {
        const int blocks = (nA * 32 + 255) / 256;
        aggregate_kernel<<<blocks, 256>>>(
            (const __half2*)mh_ptr, (float2*)z_ptr, 0, nA);
    }
    cudaEventRecord(ev_aggA, (cudaStream_t)0);

    // ---- partition B on s_b: aggB overlaps mlp2A (different pipes) ----
    cudaStreamWaitEvent(s_b, ev_aggA, 0);
    {
        const int blocks = ((n - nA) * 32 + 255) / 256;
        aggregate_kernel<<<blocks, 256, 0, s_b>>>(
            (const __half2*)mh_ptr, (float2*)z_ptr, nA, n);
    }
    mlp2_mma_kernel<float><<<mlpB_blocks, 256, SMEM_MMA_BYTES, s_b>>>(
        z_ptr, U1, c1, U2, c2, out, nA, n);
    cudaEventRecord(ev_B, s_b);

    // ---- partition A MLP (main stream, concurrent with aggB) ----
    mlp2_mma_kernel<float><<<mlpA_blocks, 256, SMEM_MMA_BYTES>>>(
        z_ptr, U1, c1, U2, c2, out, 0, nA);

    // ---- join ----
    cudaStreamWaitEvent((cudaStream_t)0, ev_B, 0);
}

// round 17
// speedup vs baseline: 1.1422x; 1.1422x over previous
#include <cuda_runtime.h>
#include <cuda_fp16.h>
#include <cstdint>

#define D 64
#define NMAX 50000
#define TILE_M 128
#define LDX 72            // halves per SMEM row: 144B = 9*16B -> ldmatrix conflict-free
#define CAP 128           // per-node bucket capacity (max degree ~60, 14-sigma margin)

// ---------------- device scratch (no allocation allowed) ----------------
__device__ __half g_mh[NMAX * D];        // per-node message table (fp16)
__device__ float  g_z[NMAX * D];         // segment-sum result (fp32)
__device__ int    g_cnt[NMAX];           // per-node edge counts
__device__ int    g_bucket[NMAX * CAP];  // per-node src lists (fixed stride)

// SMEM: Xh[128][LDX] fp16 (reused for H1), W1h/W2h[64][LDX] fp16, b1s/b2s[64] f32
#define SMEM_MMA_BYTES (128 * LDX * 2 + 2 * 64 * LDX * 2 + 2 * 64 * 4 + 64)

// ---------------- packed fp32x2 helpers (sm_103a) ----------------
__device__ __forceinline__ unsigned long long dup_f32x2(float x) {
    unsigned long long r;
    asm("mov.b64 %0, {%1, %1};" : "=l"(r) : "f"(x));
    return r;
}
__device__ __forceinline__ unsigned long long pack_f32x2(float x, float y) {
    unsigned long long r;
    asm("mov.b64 %0, {%1, %2};" : "=l"(r) : "f"(x), "f"(y));
    return r;
}
__device__ __forceinline__ void unpack_f32x2(unsigned long long v, float& x, float& y) {
    asm("mov.b64 {%0, %1}, %2;" : "=f"(x), "=f"(y) : "l"(v));
}
#define FMA2(d, a, b) \
    asm("fma.rn.f32x2 %0, %1, %2, %0;" : "+l"(d) : "l"(a), "l"(b))

// ---------------- PTX helpers ----------------
__device__ __forceinline__ uint32_t smem_u32(const void* p) {
    uint32_t a;
    asm("{ .reg .u64 t; cvta.to.shared.u64 t, %1; cvt.u32.u64 %0, t; }"
        : "=r"(a) : "l"(p));
    return a;
}
__device__ __forceinline__ void ldsm_x4(uint32_t& r0, uint32_t& r1,
                                        uint32_t& r2, uint32_t& r3, uint32_t addr) {
    asm volatile("ldmatrix.sync.aligned.m8n8.x4.shared.b16 {%0,%1,%2,%3}, [%4];"
                 : "=r"(r0), "=r"(r1), "=r"(r2), "=r"(r3) : "r"(addr));
}
__device__ __forceinline__ void ldsm_x2t(uint32_t& r0, uint32_t& r1, uint32_t addr) {
    asm volatile("ldmatrix.sync.aligned.m8n8.x2.trans.shared.b16 {%0,%1}, [%2];"
                 : "=r"(r0), "=r"(r1) : "r"(addr));
}
__device__ __forceinline__ void mma16816(float& d0, float& d1, float& d2, float& d3,
                                         uint32_t a0, uint32_t a1, uint32_t a2, uint32_t a3,
                                         uint32_t b0, uint32_t b1) {
    asm volatile(
        "mma.sync.aligned.m16n8k16.row.col.f32.f16.f16.f32 "
        "{%0,%1,%2,%3}, {%4,%5,%6,%7}, {%8,%9}, {%0,%1,%2,%3};"
        : "+f"(d0), "+f"(d1), "+f"(d2), "+f"(d3)
        : "r"(a0), "r"(a1), "r"(a2), "r"(a3), "r"(b0), "r"(b1));
}

// ---------------------------------------------------------------------------
// Tensor-core 2-layer MLP: out = relu(relu(X@W1+b1)@W2+b2).
// ILP layout: f outer / nt inner. Weight staging vectorized (float4).
// ---------------------------------------------------------------------------
template <typename OutT>
__global__ __launch_bounds__(256) void mlp2_mma_kernel(
    const float* __restrict__ in,
    const float* __restrict__ W1, const float* __restrict__ b1,
    const float* __restrict__ W2, const float* __restrict__ b2,
    OutT* __restrict__ out, int n)
{
    extern __shared__ __align__(16) char sm_raw[];
    __half* Xh  = (__half*)sm_raw;            // 128 x LDX (reused as H1)
    __half* W1h = Xh + 128 * LDX;             // 64 x LDX
    __half* W2h = W1h + 64 * LDX;             // 64 x LDX
    float*  b1s = (float*)(W2h + 64 * LDX);
    float*  b2s = b1s + 64;

    const int tid  = threadIdx.x;
    const int lane = tid & 31;
    const int wid  = tid >> 5;
    const int m0   = blockIdx.x * TILE_M;

    // ---- stage X fp32 -> fp16 (issued first so gmem loads overlap W staging) ----
#pragma unroll
    for (int p = tid; p < TILE_M * 16; p += 256) {
        const int r = p >> 4, q = p & 15;
        float4 v = make_float4(0.f, 0.f, 0.f, 0.f);
        if (m0 + r < n) v = ((const float4*)in)[(size_t)(m0 + r) * 16 + q];
        __half2* dp = (__half2*)&Xh[r * LDX + q * 4];
        dp[0] = __floats2half2_rn(v.x, v.y);
        dp[1] = __floats2half2_rn(v.z, v.w);
    }

    // ---- stage weights fp32 -> fp16 (float4 vectorized: 4 iters) ----
#pragma unroll
    for (int p = tid; p < 1024; p += 256) {
        const float4 w1 = ((const float4*)W1)[p];
        const float4 w2 = ((const float4*)W2)[p];
        const int r = p >> 4;
        const int c = (p & 15) * 4;
        __half2* d1 = (__half2*)&W1h[r * LDX + c];
        d1[0] = __floats2half2_rn(w1.x, w1.y);
        d1[1] = __floats2half2_rn(w1.z, w1.w);
        __half2* d2 = (__half2*)&W2h[r * LDX + c];
        d2[0] = __floats2half2_rn(w2.x, w2.y);
        d2[1] = __floats2half2_rn(w2.z, w2.w);
    }
    if (tid < 64) {
        b1s[tid] = b1[tid];
        b2s[tid] = b2[tid];
    }
    __syncthreads();

    const int mrow = wid * 16;
    const uint32_t xrow =
        smem_u32(Xh) + (uint32_t)(((mrow + (lane & 15)) * LDX + (lane >> 4) * 8) << 1);
    const uint32_t w1b = smem_u32(W1h);
    const uint32_t w2b = smem_u32(W2h);
    const int gid = lane >> 2;
    const int tig = lane & 3;

    uint32_t a[4][4];
    float acc[8][4];   // [nt][frag]

    // ================= Layer 1 =================
#pragma unroll
    for (int f = 0; f < 4; f++)
        ldsm_x4(a[f][0], a[f][1], a[f][2], a[f][3], xrow + (uint32_t)((f * 16) << 1));

#pragma unroll
    for (int nt = 0; nt < 8; nt++)
#pragma unroll
        for (int q = 0; q < 4; q++) acc[nt][q] = 0.f;

#pragma unroll
    for (int f = 0; f < 4; f++) {
        uint32_t B[8][2];
        const uint32_t wrow = w1b + (uint32_t)(((f * 16 + (lane & 15)) * LDX) << 1);
#pragma unroll
        for (int nt = 0; nt < 8; nt++)
            ldsm_x2t(B[nt][0], B[nt][1], wrow + (uint32_t)((nt * 8) << 1));
#pragma unroll
        for (int nt = 0; nt < 8; nt++)
            mma16816(acc[nt][0], acc[nt][1], acc[nt][2], acc[nt][3],
                     a[f][0], a[f][1], a[f][2], a[f][3], B[nt][0], B[nt][1]);
    }

#pragma unroll
    for (int nt = 0; nt < 8; nt++) {
        const int c = nt * 8 + tig * 2;
        const float2 bb = *(const float2*)&b1s[c];
        const __half2 h01 = __floats2half2_rn(fmaxf(acc[nt][0] + bb.x, 0.f),
                                              fmaxf(acc[nt][1] + bb.y, 0.f));
        const __half2 h23 = __floats2half2_rn(fmaxf(acc[nt][2] + bb.x, 0.f),
                                              fmaxf(acc[nt][3] + bb.y, 0.f));
        *(__half2*)&Xh[(mrow + gid) * LDX + c]     = h01;
        *(__half2*)&Xh[(mrow + gid + 8) * LDX + c] = h23;
    }
    __syncwarp();

    // ================= Layer 2 =================
#pragma unroll
    for (int f = 0; f < 4; f++)
        ldsm_x4(a[f][0], a[f][1], a[f][2], a[f][3], xrow + (uint32_t)((f * 16) << 1));

#pragma unroll
    for (int nt = 0; nt < 8; nt++)
#pragma unroll
        for (int q = 0; q < 4; q++) acc[nt][q] = 0.f;

#pragma unroll
    for (int f = 0; f < 4; f++) {
        uint32_t B[8][2];
        const uint32_t wrow = w2b + (uint32_t)(((f * 16 + (lane & 15)) * LDX) << 1);
#pragma unroll
        for (int nt = 0; nt < 8; nt++)
            ldsm_x2t(B[nt][0], B[nt][1], wrow + (uint32_t)((nt * 8) << 1));
#pragma unroll
        for (int nt = 0; nt < 8; nt++)
            mma16816(acc[nt][0], acc[nt][1], acc[nt][2], acc[nt][3],
                     a[f][0], a[f][1], a[f][2], a[f][3], B[nt][0], B[nt][1]);
    }

#pragma unroll
    for (int nt = 0; nt < 8; nt++) {
        const int c = nt * 8 + tig * 2;
        const float2 bb = *(const float2*)&b2s[c];
        const float h0 = fmaxf(acc[nt][0] + bb.x, 0.f);
        const float h1 = fmaxf(acc[nt][1] + bb.y, 0.f);
        const float h2 = fmaxf(acc[nt][2] + bb.x, 0.f);
        const float h3 = fmaxf(acc[nt][3] + bb.y, 0.f);
        const int r0 = m0 + mrow + gid;
        const int r1 = r0 + 8;
        if constexpr (sizeof(OutT) == 4) {
            if (r0 < n) *(float2*)&out[(size_t)r0 * 64 + c] = make_float2(h0, h1);
            if (r1 < n) *(float2*)&out[(size_t)r1 * 64 + c] = make_float2(h2, h3);
        } else {
            if (r0 < n) *(__half2*)&out[(size_t)r0 * 64 + c] = __floats2half2_rn(h0, h1);
            if (r1 < n) *(__half2*)&out[(size_t)r1 * 64 + c] = __floats2half2_rn(h2, h3);
        }
    }
}

// ---------------------------------------------------------------------------
// Single-pass bucketing: pos = cnt[dst]++; bucket[dst*CAP+pos] = src.
// ---------------------------------------------------------------------------
__global__ __launch_bounds__(256) void bucket_kernel(
    const int* __restrict__ src, const int* __restrict__ dst, int e)
{
    int i = blockIdx.x * blockDim.x + threadIdx.x;
    if (i < e) {
        const int d = dst[i];
        const int pos = atomicAdd(&g_cnt[d], 1);
        if (pos < CAP)  // overflow impossible for Binomial(E,1/N) degrees (14 sigma)
            g_bucket[d * CAP + pos] = src[i];
    }
}

// ---------------------------------------------------------------------------
// Bucket aggregation, 2 edges per warp round:
// 16 lanes/edge, lane loads uint2 (4 cols, row stride = 16 uint2), masked
// f32x2 accumulation, cross-half shfl_xor(16) reduction, lanes 0-15 write
// one float4 (coalesced 256B/node).
// ---------------------------------------------------------------------------
__global__ __launch_bounds__(256) void aggregate_kernel(
    const uint2* __restrict__ m4, float* __restrict__ z, int n)
{
    const int node = (blockIdx.x * 256 + threadIdx.x) >> 5;
    const int lane = threadIdx.x & 31;
    if (node >= n) return;

    const int cnt = min(g_cnt[node], CAP);
    const int s0 = node * CAP;
    const int half = lane >> 4;      // which edge of the pair
    const int colg = lane & 15;      // column group: cols 4*colg .. 4*colg+3

    unsigned long long acc01 = 0ULL, acc23 = 0ULL;

    for (int base = 0; base < cnt; base += 32) {
        const int c = min(32, cnt - base);
        int si = (lane < c) ? g_bucket[s0 + base + lane] : 0;
#pragma unroll 4
        for (int j = 0; j < c; j += 2) {
            const int idx = j + half;
            const int s = __shfl_sync(0xffffffffu, si, idx & 31);
            const float mval = (idx < c) ? 1.f : 0.f;   // mask odd tail
            // row = 64 halves = 16 uint2; this lane reads uint2 #colg (4 halves)
            const uint2 u = __ldg(&m4[(size_t)s * 16 + colg]);
            const float2 f0 = __half22float2(*(const __half2*)&u.x);
            const float2 f1 = __half22float2(*(const __half2*)&u.y);
            const unsigned long long mm = dup_f32x2(mval);
            const unsigned long long a01 = pack_f32x2(f0.x, f0.y);
            const unsigned long long a23 = pack_f32x2(f1.x, f1.y);
            FMA2(acc01, a01, mm);
            FMA2(acc23, a23, mm);
        }
    }

    float a0, a1, a2, a3;
    unpack_f32x2(acc01, a0, a1);
    unpack_f32x2(acc23, a2, a3);
    a0 += __shfl_xor_sync(0xffffffffu, a0, 16);
    a1 += __shfl_xor_sync(0xffffffffu, a1, 16);
    a2 += __shfl_xor_sync(0xffffffffu, a2, 16);
    a3 += __shfl_xor_sync(0xffffffffu, a3, 16);

    if (lane < 16)
        *(float4*)&z[(size_t)node * 64 + colg * 4] = make_float4(a0, a1, a2, a3);
}

// ---------------------------------------------------------------------------
extern "C" void kernel_launch(void* const* d_in, const int* in_sizes, int n_in,
                              void* d_out, int out_size) {
    const float* y   = (const float*)d_in[0];
    const int*   src = (const int*)d_in[1];
    const int*   dst = (const int*)d_in[2];
    const float* W1  = (const float*)d_in[3];
    const float* b1  = (const float*)d_in[4];
    const float* W2  = (const float*)d_in[5];
    const float* b2  = (const float*)d_in[6];
    const float* U1  = (const float*)d_in[7];
    const float* c1  = (const float*)d_in[8];
    const float* U2  = (const float*)d_in[9];
    const float* c2  = (const float*)d_in[10];
    float* out = (float*)d_out;

    const int n = in_sizes[0] / D;
    const int e = in_sizes[1];

    __half* mh_ptr = nullptr;
    float*  z_ptr  = nullptr;
    int*    cnt_ptr = nullptr;
    cudaGetSymbolAddress((void**)&mh_ptr, g_mh);
    cudaGetSymbolAddress((void**)&z_ptr, g_z);
    cudaGetSymbolAddress((void**)&cnt_ptr, g_cnt);

    cudaFuncSetAttribute(mlp2_mma_kernel<__half>,
                         cudaFuncAttributeMaxDynamicSharedMemorySize, SMEM_MMA_BYTES);
    cudaFuncSetAttribute(mlp2_mma_kernel<float>,
                         cudaFuncAttributeMaxDynamicSharedMemorySize, SMEM_MMA_BYTES);

    static cudaStream_t s_mlp = ([] {
        cudaStream_t s;
        cudaStreamCreateWithFlags(&s, cudaStreamNonBlocking);
        return s;
    })();
    static cudaEvent_t ev_fork = ([] {
        cudaEvent_t ev;
        cudaEventCreateWithFlags(&ev, cudaEventDisableTiming);
        return ev;
    })();
    static cudaEvent_t ev_mlp1 = ([] {
        cudaEvent_t ev;
        cudaEventCreateWithFlags(&ev, cudaEventDisableTiming);
        return ev;
    })();

    const int mlp_blocks = (n + TILE_M - 1) / TILE_M;
    const int edge_blocks = (e + 255) / 256;

    // ---- fork: mlp1 on side stream, bucket pass on main stream ----
    cudaEventRecord(ev_fork, (cudaStream_t)0);
    cudaStreamWaitEvent(s_mlp, ev_fork, 0);

    // side stream: edge-message MLP (tensor cores, fp16 out)
    mlp2_mma_kernel<__half><<<mlp_blocks, 256, SMEM_MMA_BYTES, s_mlp>>>(
        y, W1, b1, W2, b2, mh_ptr, n);
    cudaEventRecord(ev_mlp1, s_mlp);

    // main stream: zero counts, then single-pass bucketing
    cudaMemsetAsync(cnt_ptr, 0, (size_t)n * sizeof(int));
    bucket_kernel<<<edge_blocks, 256>>>(src, dst, e);

    // join: aggregate needs both buckets and messages
    cudaStreamWaitEvent((cudaStream_t)0, ev_mlp1, 0);
    {
        const int blocks = (n * 32 + 255) / 256;
        aggregate_kernel<<<blocks, 256>>>((const uint2*)mh_ptr, z_ptr, n);
    }

    // node-update MLP (tensor cores, fp32 out)
    mlp2_mma_kernel<float><<<mlp_blocks, 256, SMEM_MMA_BYTES>>>(
        z_ptr, U1, c1, U2, c2, out, n);
}